// round 15
// baseline (speedup 1.0000x reference)
#include <cuda_runtime.h>
#include <math.h>

#define TT  50
#define BB  1024
#define BEL 200
#define ST  30
#define ACT 8
#define EMB 1024

static const size_t OFF_B  = 0;
static const size_t OFF_PS = (size_t)TT * BB * BEL;
static const size_t SZ30   = (size_t)TT * BB * ST;
static const size_t OFF_MP = OFF_PS + SZ30;
static const size_t OFF_SP = OFF_MP + SZ30;
static const size_t OFF_PO = OFF_SP + SZ30;
static const size_t OFF_MQ = OFF_PO + SZ30;
static const size_t OFF_SQ = OFF_MQ + SZ30;

__device__ __align__(16) float g_obs[(size_t)TT * BB * BEL];
__device__ __align__(16) float g_Wg2[240000];  // [k4][tc(600)][2cols][4k]; tc<300: W_ih else W_hh
__device__ __align__(16) float g_Wsa[8000];    // [k4(10)][j(200)][4k], K padded 38->40 (state+action)
__device__ __align__(16) float g_Wh2[80000];   // [k4][p(200)][2cols][4k]; p<100: W_bp else W_bq_b
__device__ __align__(16) float g_Wo4[24000];   // [k4][g(120)][4k]; g<60: W_sp else W_sq

typedef unsigned long long u64;

__device__ __forceinline__ void ffma2(u64& acc, u64 a, u64 b) {
    asm("fma.rn.f32x2 %0, %1, %2, %0;" : "+l"(acc) : "l"(a), "l"(b));
}
__device__ __forceinline__ float hsum2(u64 v) {
    float lo, hi;
    asm("mov.b64 {%0,%1}, %2;" : "=f"(lo), "=f"(hi) : "l"(v));
    return lo + hi;
}
__device__ __forceinline__ float sigm(float x) { return 1.f / (1.f + __expf(-x)); }
__device__ __forceinline__ float tanhfast(float x) { return 1.f - 2.f / (__expf(2.f * x) + 1.f); }
__device__ __forceinline__ float softplusf(float x) {
    return fmaxf(x, 0.f) + log1pf(__expf(-fabsf(x)));
}

// ---------------------------------------------------------------------------
#define PREP_N 352000
__global__ void k_prep(const float* __restrict__ W_sa, const float* __restrict__ W_ih,
                       const float* __restrict__ W_hh, const float* __restrict__ W_bp,
                       const float* __restrict__ W_sp, const float* __restrict__ W_bq,
                       const float* __restrict__ W_sq) {
    int idx = blockIdx.x * blockDim.x + threadIdx.x;
    if (idx >= PREP_N) return;
    if (idx < 240000) {  // g_Wg2
        int kk = idx & 3, t1 = idx >> 2;
        int cc = t1 & 1, t2 = t1 >> 1;
        int tc = t2 % 600, k4 = t2 / 600, k = 4 * k4 + kk;
        g_Wg2[idx] = (tc < 300) ? W_ih[(2 * tc + cc) * 200 + k]
                                : W_hh[(2 * (tc - 300) + cc) * 200 + k];
        return;
    }
    idx -= 240000;
    if (idx < 8000) {    // g_Wsa
        int kk = idx & 3, t = idx >> 2;
        int j = t % 200, k4 = t / 200, k = 4 * k4 + kk;
        g_Wsa[idx] = (k < 38) ? W_sa[j * 38 + k] : 0.f;
        return;
    }
    idx -= 8000;
    if (idx < 80000) {   // g_Wh2
        int kk = idx & 3, t1 = idx >> 2;
        int cc = t1 & 1, t2 = t1 >> 1;
        int p = t2 % 200, k4 = t2 / 200, k = 4 * k4 + kk;
        g_Wh2[idx] = (p < 100) ? W_bp[(2 * p + cc) * 200 + k]
                               : W_bq[(size_t)(2 * (p - 100) + cc) * 1224 + k];
        return;
    }
    idx -= 80000;
    {                    // g_Wo4
        int kk = idx & 3, t = idx >> 2;
        int g = t % 120, k4 = t / 120, k = 4 * k4 + kk;
        g_Wo4[idx] = (g < 60) ? W_sp[g * 200 + k] : W_sq[(g - 60) * 200 + k];
    }
}

// ncu-window alignment dummy (4-kernel graphs profile the 4th kernel = k_scan).
__global__ void k_mark() {}

// ---------------------------------------------------------------------------
// Obs GEMM: unrolled-by-2 double buffer (compile-time buffer indices),
// 320 threads, tile 4x10, 2 blocks/SM.
// ---------------------------------------------------------------------------
__global__ __launch_bounds__(320, 2) void k_obs_gemm(const float* __restrict__ A,
                                                     const float* __restrict__ W_bq,
                                                     const float* __restrict__ b_bq) {
    __shared__ __align__(16) float As[2][64 * 20];
    __shared__ __align__(16) float Bs[2][200 * 18];
    const int tid = threadIdx.x;
    const size_t row0 = (size_t)blockIdx.x * 64;
    const int r0 = (tid / 20) * 4, c0 = (tid % 20) * 10;
    u64 acc[4][10];
#pragma unroll
    for (int i = 0; i < 4; i++)
#pragma unroll
        for (int j = 0; j < 10; j++) acc[i][j] = 0ULL;

    const int arow = tid >> 2, ak4 = tid & 3;
    const float* aptr = &A[(row0 + arow) * EMB + ak4 * 4];
    // B loader lanes (idx = tid, tid+320; 800 total, so nb = 2 or 3)
    const int bcol0 = tid >> 2, be0 = (tid & 3) * 4;
    const int bcol1 = (tid + 320) >> 2, be1 = ((tid + 320) & 3) * 4;
    const int bcol2 = (tid + 640) >> 2, be2 = ((tid + 640) & 3) * 4;
    const bool hasb2 = (tid + 640) < 800;
    const float* wb0 = &W_bq[(size_t)bcol0 * 1224 + 200 + be0];
    const float* wb1 = &W_bq[(size_t)bcol1 * 1224 + 200 + be1];
    const float* wb2 = hasb2 ? &W_bq[(size_t)bcol2 * 1224 + 200 + be2] : wb0;

    float4 pa, pb0, pb1, pb2;
#define GLOAD(kt)                                                      \
    {                                                                  \
        if (tid < 256) pa = *(const float4*)(aptr + (kt) * 16);        \
        pb0 = *(const float4*)(wb0 + (kt) * 16);                       \
        pb1 = *(const float4*)(wb1 + (kt) * 16);                       \
        if (hasb2) pb2 = *(const float4*)(wb2 + (kt) * 16);            \
    }
#define SSTORE(buf)                                                     \
    {                                                                   \
        if (tid < 256) *(float4*)&As[buf][arow * 20 + ak4 * 4] = pa;    \
        Bs[buf][bcol0 * 18 + be0 + 0] = pb0.x;                          \
        Bs[buf][bcol0 * 18 + be0 + 1] = pb0.y;                          \
        Bs[buf][bcol0 * 18 + be0 + 2] = pb0.z;                          \
        Bs[buf][bcol0 * 18 + be0 + 3] = pb0.w;                          \
        Bs[buf][bcol1 * 18 + be1 + 0] = pb1.x;                          \
        Bs[buf][bcol1 * 18 + be1 + 1] = pb1.y;                          \
        Bs[buf][bcol1 * 18 + be1 + 2] = pb1.z;                          \
        Bs[buf][bcol1 * 18 + be1 + 3] = pb1.w;                          \
        if (hasb2) {                                                    \
            Bs[buf][bcol2 * 18 + be2 + 0] = pb2.x;                      \
            Bs[buf][bcol2 * 18 + be2 + 1] = pb2.y;                      \
            Bs[buf][bcol2 * 18 + be2 + 2] = pb2.z;                      \
            Bs[buf][bcol2 * 18 + be2 + 3] = pb2.w;                      \
        }                                                               \
    }
#define COMPUTE(buf)                                                          \
    {                                                                         \
        _Pragma("unroll")                                                     \
        for (int kp = 0; kp < 8; kp++) {                                      \
            u64 a2[4], b2[10];                                                \
            _Pragma("unroll")                                                 \
            for (int i = 0; i < 4; i++)                                       \
                a2[i] = *(const u64*)&As[buf][(r0 + i) * 20 + 2 * kp];        \
            _Pragma("unroll")                                                 \
            for (int j = 0; j < 10; j++)                                      \
                b2[j] = *(const u64*)&Bs[buf][(c0 + j) * 18 + 2 * kp];        \
            _Pragma("unroll")                                                 \
            for (int i = 0; i < 4; i++)                                       \
                _Pragma("unroll")                                             \
                for (int j = 0; j < 10; j++) ffma2(acc[i][j], a2[i], b2[j]);  \
        }                                                                     \
    }

    GLOAD(0) SSTORE(0)
    __syncthreads();
    for (int it = 0; it < 32; it++) {
        GLOAD(2 * it + 1)
        COMPUTE(0)
        SSTORE(1)
        __syncthreads();
        const bool hn = (2 * it + 2) < 64;
        if (hn) GLOAD(2 * it + 2)
        COMPUTE(1)
        if (hn) SSTORE(0)
        __syncthreads();
    }
#pragma unroll
    for (int i = 0; i < 4; i++)
#pragma unroll
        for (int j = 0; j < 10; j++)
            g_obs[(row0 + r0 + i) * BEL + c0 + j] = hsum2(acc[i][j]) + b_bq[c0 + j];
#undef GLOAD
#undef SSTORE
#undef COMPUTE
}

// ---------------------------------------------------------------------------
// Persistent scan (R14 frozen — current best).
// ---------------------------------------------------------------------------
#define SCAN_SMEM (18520 * 4)

__global__ __launch_bounds__(640, 1) void k_scan(
    const float* __restrict__ nonterm, const float* __restrict__ prev_state,
    const float* __restrict__ prev_belief, const float* __restrict__ actions,
    const float* __restrict__ noise_p, const float* __restrict__ noise_q,
    const float* __restrict__ b_sa, const float* __restrict__ b_ih,
    const float* __restrict__ b_hh, const float* __restrict__ b_bp,
    const float* __restrict__ b_sp, const float* __restrict__ b_sq,
    float* __restrict__ out) {
    extern __shared__ float sm[];
    float* s_sh = sm;            // 8x40 = 320
    float* hid  = sm + 320;      // 1600
    float* bel  = hid + 1600;    // 1600
    float* gig  = bel + 1600;    // 9600
    float* obs  = gig + 9600;    // 1600
    float* hp   = obs + 1600;    // 1600
    float* hq   = hp + 1600;     // 1600
    float* bias = hq + 1600;     // 120
    float* nbuf = bias + 120;    // 480

    const int tid = threadIdx.x;
    const int b0 = blockIdx.x * 8;

    float r_bsa = 0.f, r_bir = 0.f, r_biz = 0.f, r_bin = 0.f;
    float r_bhr = 0.f, r_bhz = 0.f, r_bhn = 0.f, r_bbp = 0.f;
    if (tid < 200) {
        r_bsa = b_sa[tid];
        r_bir = b_ih[tid]; r_biz = b_ih[200 + tid]; r_bin = b_ih[400 + tid];
        r_bhr = b_hh[tid]; r_bhz = b_hh[200 + tid]; r_bhn = b_hh[400 + tid];
        r_bbp = b_bp[tid];
    }
    if (tid < 120) bias[tid] = (tid < 60) ? b_sp[tid] : b_sq[tid - 60];

    for (int idx = tid; idx < 8 * BEL; idx += 640) {
        int bb = idx / BEL, j = idx - bb * BEL;
        bel[idx] = prev_belief[(size_t)(b0 + bb) * BEL + j];
    }
    if (tid < 320) {
        int bb = tid / 40, c = tid % 40;
        float v = 0.f;
        if (c < 30)      v = prev_state[(size_t)(b0 + bb) * ST + c] * nonterm[b0 + bb];
        else if (c < 38) v = actions[(size_t)(b0 + bb) * ACT + (c - 30)];
        s_sh[tid] = v;
    } else if (tid >= 320) {
        for (int i = tid - 320; i < 400; i += 320)
            *(float4*)&obs[i * 4] = *(const float4*)&g_obs[(size_t)b0 * BEL + i * 4];
    }
    __syncthreads();

    for (int t = 0; t < TT; t++) {
        // ===== PhA =====
        if (tid < 200) {
            u64 acc[8];
#pragma unroll
            for (int bb = 0; bb < 8; bb++) acc[bb] = 0ULL;
            const char* wp = (const char*)g_Wsa + tid * 16;
#pragma unroll
            for (int k4 = 0; k4 < 10; k4++) {
                ulonglong2 w = __ldg((const ulonglong2*)(wp + k4 * 3200));
                const char* sp = (const char*)s_sh + k4 * 16;
#pragma unroll
                for (int bb = 0; bb < 8; bb++) {
                    ulonglong2 s = *(const ulonglong2*)(sp + bb * 160);
                    ffma2(acc[bb], s.x, w.x);
                    ffma2(acc[bb], s.y, w.y);
                }
            }
#pragma unroll
            for (int bb = 0; bb < 8; bb++)
                hid[bb * 200 + tid] = fmaxf(hsum2(acc[bb]) + r_bsa, 0.f);
        }
        __syncthreads();

        // ===== PhB =====
        if (tid < 600) {
            const char* src = (const char*)((tid < 300) ? hid : bel);
            const char* wp = (const char*)g_Wg2 + tid * 32;
            u64 accA[8], accB[8];
#pragma unroll
            for (int bb = 0; bb < 8; bb++) { accA[bb] = 0ULL; accB[bb] = 0ULL; }
            ulonglong2 w0a = *(const ulonglong2*)wp;
            ulonglong2 w0b = *(const ulonglong2*)(wp + 16);
            ulonglong2 w1a = *(const ulonglong2*)(wp + 19200);
            ulonglong2 w1b = *(const ulonglong2*)(wp + 19216);
#pragma unroll 5
            for (int k4 = 0; k4 < 50; k4++) {
                ulonglong2 wa = w0a, wb = w0b;
                w0a = w1a; w0b = w1b;
                if (k4 + 2 < 50) {
                    w1a = *(const ulonglong2*)(wp + (k4 + 2) * 19200);
                    w1b = *(const ulonglong2*)(wp + (k4 + 2) * 19200 + 16);
                }
                const char* sp = src + k4 * 16;
#pragma unroll
                for (int bb = 0; bb < 8; bb++) {
                    ulonglong2 h = *(const ulonglong2*)(sp + bb * 800);
                    ffma2(accA[bb], h.x, wa.x); ffma2(accA[bb], h.y, wa.y);
                    ffma2(accB[bb], h.x, wb.x); ffma2(accB[bb], h.y, wb.y);
                }
            }
            int p = (tid < 300) ? tid : tid - 300;
            float* dst = (tid < 300) ? gig : (gig + 4800);
#pragma unroll
            for (int bb = 0; bb < 8; bb++) {
                dst[bb * 600 + 2 * p]     = hsum2(accA[bb]);
                dst[bb * 600 + 2 * p + 1] = hsum2(accB[bb]);
            }
        }
        __syncthreads();

        // ===== PhC =====
        if (tid < 200) {
            const int j = tid;
            const float* gh = gig + 4800;
#pragma unroll
            for (int bb = 0; bb < 8; bb++) {
                float r = sigm(gig[bb * 600 + j] + r_bir + gh[bb * 600 + j] + r_bhr);
                float z = sigm(gig[bb * 600 + 200 + j] + r_biz + gh[bb * 600 + 200 + j] + r_bhz);
                float n = tanhfast(gig[bb * 600 + 400 + j] + r_bin +
                                   r * (gh[bb * 600 + 400 + j] + r_bhn));
                float nb = (1.f - z) * n + z * bel[bb * 200 + j];
                bel[bb * 200 + j] = nb;
                out[OFF_B + ((size_t)t * BB + b0 + bb) * BEL + j] = nb;
            }
        }
        __syncthreads();

        // ===== PhD =====
        if (tid < 400) {
            const int p = tid % 200;
            const int half = tid / 200;
            const char* wp = (const char*)g_Wh2 + p * 32;
            u64 accA[8], accB[8];
#pragma unroll
            for (int bb = 0; bb < 8; bb++) { accA[bb] = 0ULL; accB[bb] = 0ULL; }
            const int kb = half * 25;
            const char* wpk = wp + kb * 6400;
            ulonglong2 w0a = *(const ulonglong2*)wpk;
            ulonglong2 w0b = *(const ulonglong2*)(wpk + 16);
            ulonglong2 w1a = *(const ulonglong2*)(wpk + 6400);
            ulonglong2 w1b = *(const ulonglong2*)(wpk + 6416);
            const char* sb = (const char*)bel + kb * 16;
#pragma unroll 5
            for (int kk = 0; kk < 25; kk++) {
                ulonglong2 wa = w0a, wb = w0b;
                w0a = w1a; w0b = w1b;
                if (kk + 2 < 25) {
                    w1a = *(const ulonglong2*)(wpk + (kk + 2) * 6400);
                    w1b = *(const ulonglong2*)(wpk + (kk + 2) * 6400 + 16);
                }
                const char* sp = sb + kk * 16;
#pragma unroll
                for (int bb = 0; bb < 8; bb++) {
                    ulonglong2 h = *(const ulonglong2*)(sp + bb * 800);
                    ffma2(accA[bb], h.x, wa.x); ffma2(accA[bb], h.y, wa.y);
                    ffma2(accB[bb], h.x, wb.x); ffma2(accB[bb], h.y, wb.y);
                }
            }
#pragma unroll
            for (int bb = 0; bb < 8; bb++) {
                gig[half * 3200 + bb * 400 + 2 * p]     = hsum2(accA[bb]);
                gig[half * 3200 + bb * 400 + 2 * p + 1] = hsum2(accB[bb]);
            }
        } else if (tid < 520) {
            int i = tid - 400;
            size_t base = ((size_t)t * BB + b0) * ST;
            if (i < 60) *(float4*)&nbuf[i * 4] = *(const float4*)&noise_p[base + i * 4];
            else {
                int j = i - 60;
                *(float4*)&nbuf[240 + j * 4] = *(const float4*)&noise_q[base + j * 4];
            }
        }
        __syncthreads();

        // ===== reduce -> hp/hq =====
        if (tid < 400) {
#pragma unroll
            for (int bb = 0; bb < 8; bb++) {
                float v = gig[bb * 400 + tid] + gig[3200 + bb * 400 + tid];
                if (tid < 200) hp[bb * 200 + tid] = fmaxf(v + r_bbp, 0.f);
                else hq[bb * 200 + tid - 200] = fmaxf(v + obs[bb * 200 + tid - 200], 0.f);
            }
        }
        __syncthreads();

        // ===== PhE =====
        if (tid < 600) {
            const int g = tid % 120, q = tid / 120;
            const float* srcf = (g < 60) ? hp : hq;
            u64 acc[8];
#pragma unroll
            for (int bb = 0; bb < 8; bb++) acc[bb] = 0ULL;
            const char* wp = (const char*)g_Wo4 + q * 19200 + g * 16;
            const char* sb = (const char*)srcf + q * 160;
#pragma unroll
            for (int kk = 0; kk < 10; kk++) {
                ulonglong2 w = __ldg((const ulonglong2*)(wp + kk * 1920));
                const char* sp = sb + kk * 16;
#pragma unroll
                for (int bb = 0; bb < 8; bb++) {
                    ulonglong2 h = *(const ulonglong2*)(sp + bb * 800);
                    ffma2(acc[bb], h.x, w.x);
                    ffma2(acc[bb], h.y, w.y);
                }
            }
#pragma unroll
            for (int bb = 0; bb < 8; bb++)
                gig[q * 960 + bb * 120 + g] = hsum2(acc[bb]);
        }
        __syncthreads();

        // ===== PhF =====
        if (tid < 240) {
            const int bb = tid / 30, i = tid - bb * 30;
            size_t gidx = ((size_t)t * BB + b0 + bb) * ST + i;
            float np = nbuf[bb * 30 + i], nq = nbuf[240 + bb * 30 + i];
            float mp = bias[i], spr = bias[30 + i], mq = bias[60 + i], sqr = bias[90 + i];
#pragma unroll
            for (int q = 0; q < 5; q++) {
                mp  += gig[q * 960 + bb * 120 + i];
                spr += gig[q * 960 + bb * 120 + 30 + i];
                mq  += gig[q * 960 + bb * 120 + 60 + i];
                sqr += gig[q * 960 + bb * 120 + 90 + i];
            }
            float spv = softplusf(spr) + 0.1f;
            float sqv = softplusf(sqr) + 0.1f;
            float po  = fmaf(sqv, nq, mq);
            out[OFF_MP + gidx] = mp;
            out[OFF_SP + gidx] = spv;
            out[OFF_PS + gidx] = fmaf(spv, np, mp);
            out[OFF_MQ + gidx] = mq;
            out[OFF_SQ + gidx] = sqv;
            out[OFF_PO + gidx] = po;
            if (t + 1 < TT)
                s_sh[bb * 40 + i] = po * nonterm[(size_t)(t + 1) * BB + b0 + bb];
        } else if (tid < 304) {
            int idx = tid - 240, bb = idx >> 3, i = idx & 7;
            if (t + 1 < TT)
                s_sh[bb * 40 + 30 + i] = actions[((size_t)(t + 1) * BB + b0 + bb) * ACT + i];
        } else if (tid >= 320) {
            if (t + 1 < TT) {
                for (int i = tid - 320; i < 400; i += 320)
                    *(float4*)&obs[i * 4] =
                        *(const float4*)&g_obs[((size_t)(t + 1) * BB + b0) * BEL + i * 4];
            }
        }
        __syncthreads();
    }
}

// ---------------------------------------------------------------------------
extern "C" void kernel_launch(void* const* d_in, const int* in_sizes, int n_in,
                              void* d_out, int out_size) {
    const float* prev_state   = (const float*)d_in[0];
    const float* actions      = (const float*)d_in[1];
    const float* prev_belief  = (const float*)d_in[2];
    const float* observations = (const float*)d_in[3];
    const float* nonterm      = (const float*)d_in[4];
    const float* noise_p      = (const float*)d_in[5];
    const float* noise_q      = (const float*)d_in[6];
    const float* W_sa = (const float*)d_in[7];  const float* b_sa = (const float*)d_in[8];
    const float* W_ih = (const float*)d_in[9];  const float* b_ih = (const float*)d_in[10];
    const float* W_hh = (const float*)d_in[11]; const float* b_hh = (const float*)d_in[12];
    const float* W_bp = (const float*)d_in[13]; const float* b_bp = (const float*)d_in[14];
    const float* W_sp = (const float*)d_in[15]; const float* b_sp = (const float*)d_in[16];
    const float* W_bq = (const float*)d_in[17]; const float* b_bq = (const float*)d_in[18];
    const float* W_sq = (const float*)d_in[19]; const float* b_sq = (const float*)d_in[20];
    float* out = (float*)d_out;
    (void)in_sizes; (void)n_in; (void)out_size;

    static int done = 0;
    if (!done) {
        cudaFuncSetAttribute(k_scan, cudaFuncAttributeMaxDynamicSharedMemorySize, SCAN_SMEM);
        done = 1;
    }
    k_prep<<<(PREP_N + 255) / 256, 256>>>(W_sa, W_ih, W_hh, W_bp, W_sp, W_bq, W_sq);
    k_mark<<<1, 32>>>();
    k_obs_gemm<<<(TT * BB) / 64, 320>>>(observations, W_bq, b_bq);
    k_scan<<<BB / 8, 640, SCAN_SMEM>>>(nonterm, prev_state, prev_belief, actions,
                                       noise_p, noise_q, b_sa, b_ih, b_hh,
                                       b_bp, b_sp, b_sq, out);
}

// round 16
// speedup vs baseline: 1.6382x; 1.6382x over previous
#include <cuda_runtime.h>
#include <math.h>

#define TT  50
#define BB  1024
#define BEL 200
#define ST  30
#define ACT 8
#define EMB 1024

static const size_t OFF_B  = 0;
static const size_t OFF_PS = (size_t)TT * BB * BEL;
static const size_t SZ30   = (size_t)TT * BB * ST;
static const size_t OFF_MP = OFF_PS + SZ30;
static const size_t OFF_SP = OFF_MP + SZ30;
static const size_t OFF_PO = OFF_SP + SZ30;
static const size_t OFF_MQ = OFF_PO + SZ30;
static const size_t OFF_SQ = OFF_MQ + SZ30;

__device__ __align__(16) float g_obs[(size_t)TT * BB * BEL];
__device__ __align__(16) float g_Wg2[240000];  // [k4][tc(600)][2cols][4k]; tc<300: W_ih else W_hh
__device__ __align__(16) float g_Wsa[8000];    // [k4(10)][j(200)][4k], K padded 38->40 (state+action)
__device__ __align__(16) float g_Wh2[80000];   // [k4][p(200)][2cols][4k]; p<100: W_bp else W_bq_b
__device__ __align__(16) float g_Wo4[24000];   // [k4][g(120)][4k]; g<60: W_sp else W_sq

typedef unsigned long long u64;

__device__ __forceinline__ void ffma2(u64& acc, u64 a, u64 b) {
    asm("fma.rn.f32x2 %0, %1, %2, %0;" : "+l"(acc) : "l"(a), "l"(b));
}
__device__ __forceinline__ float hsum2(u64 v) {
    float lo, hi;
    asm("mov.b64 {%0,%1}, %2;" : "=f"(lo), "=f"(hi) : "l"(v));
    return lo + hi;
}
__device__ __forceinline__ float sigm(float x) { return 1.f / (1.f + __expf(-x)); }
__device__ __forceinline__ float tanhfast(float x) { return 1.f - 2.f / (__expf(2.f * x) + 1.f); }
__device__ __forceinline__ float softplusf(float x) {
    return fmaxf(x, 0.f) + log1pf(__expf(-fabsf(x)));
}

// ---------------------------------------------------------------------------
#define PREP_N 352000
__global__ void k_prep(const float* __restrict__ W_sa, const float* __restrict__ W_ih,
                       const float* __restrict__ W_hh, const float* __restrict__ W_bp,
                       const float* __restrict__ W_sp, const float* __restrict__ W_bq,
                       const float* __restrict__ W_sq) {
    int idx = blockIdx.x * blockDim.x + threadIdx.x;
    if (idx >= PREP_N) return;
    if (idx < 240000) {  // g_Wg2
        int kk = idx & 3, t1 = idx >> 2;
        int cc = t1 & 1, t2 = t1 >> 1;
        int tc = t2 % 600, k4 = t2 / 600, k = 4 * k4 + kk;
        g_Wg2[idx] = (tc < 300) ? W_ih[(2 * tc + cc) * 200 + k]
                                : W_hh[(2 * (tc - 300) + cc) * 200 + k];
        return;
    }
    idx -= 240000;
    if (idx < 8000) {    // g_Wsa (state+action, K padded to 40)
        int kk = idx & 3, t = idx >> 2;
        int j = t % 200, k4 = t / 200, k = 4 * k4 + kk;
        g_Wsa[idx] = (k < 38) ? W_sa[j * 38 + k] : 0.f;
        return;
    }
    idx -= 8000;
    if (idx < 80000) {   // g_Wh2
        int kk = idx & 3, t1 = idx >> 2;
        int cc = t1 & 1, t2 = t1 >> 1;
        int p = t2 % 200, k4 = t2 / 200, k = 4 * k4 + kk;
        g_Wh2[idx] = (p < 100) ? W_bp[(2 * p + cc) * 200 + k]
                               : W_bq[(size_t)(2 * (p - 100) + cc) * 1224 + k];
        return;
    }
    idx -= 80000;
    {                    // g_Wo4
        int kk = idx & 3, t = idx >> 2;
        int g = t % 120, k4 = t / 120, k = 4 * k4 + kk;
        g_Wo4[idx] = (g < 60) ? W_sp[g * 200 + k] : W_sq[(g - 60) * 200 + k];
    }
}

// ncu-window alignment dummy (4-kernel graphs profile the 4th kernel = k_scan).
__global__ void k_mark() {}

// ---------------------------------------------------------------------------
// Obs GEMM (R3/R10/R14-proven, 320 threads, tile 4x10, double-buffered).
// ---------------------------------------------------------------------------
__global__ __launch_bounds__(320, 1) void k_obs_gemm(const float* __restrict__ A,
                                                     const float* __restrict__ W_bq,
                                                     const float* __restrict__ b_bq) {
    __shared__ __align__(16) float As[2][64 * 20];
    __shared__ __align__(16) float Bs[2][200 * 18];
    const int tid = threadIdx.x;
    const size_t row0 = (size_t)blockIdx.x * 64;
    const int r0 = (tid / 20) * 4, c0 = (tid % 20) * 10;
    u64 acc[4][10];
#pragma unroll
    for (int i = 0; i < 4; i++)
#pragma unroll
        for (int j = 0; j < 10; j++) acc[i][j] = 0ULL;
    const int arow = tid >> 2, ak4 = tid & 3;
    if (tid < 256)
        *(float4*)&As[0][arow * 20 + ak4 * 4] = *(const float4*)&A[(row0 + arow) * EMB + ak4 * 4];
    for (int idx = tid; idx < 800; idx += 320) {
        int col = idx >> 2, e4 = idx & 3;
        float4 v = *(const float4*)&W_bq[(size_t)col * 1224 + 200 + e4 * 4];
        Bs[0][col * 18 + e4 * 4 + 0] = v.x; Bs[0][col * 18 + e4 * 4 + 1] = v.y;
        Bs[0][col * 18 + e4 * 4 + 2] = v.z; Bs[0][col * 18 + e4 * 4 + 3] = v.w;
    }
    __syncthreads();
    for (int kti = 0; kti < 64; kti++) {
        const int cur = kti & 1;
        const bool hn = (kti + 1) < 64;
        float4 pa; float4 pb[3]; int nb = 0;
        if (hn) {
            int kt = (kti + 1) * 16;
            if (tid < 256) pa = *(const float4*)&A[(row0 + arow) * EMB + kt + ak4 * 4];
            for (int idx = tid; idx < 800; idx += 320) {
                int col = idx >> 2, e4 = idx & 3;
                pb[nb++] = *(const float4*)&W_bq[(size_t)col * 1224 + 200 + kt + e4 * 4];
            }
        }
#pragma unroll
        for (int kp = 0; kp < 8; kp++) {
            u64 a2[4], b2[10];
#pragma unroll
            for (int i = 0; i < 4; i++) a2[i] = *(const u64*)&As[cur][(r0 + i) * 20 + 2 * kp];
#pragma unroll
            for (int j = 0; j < 10; j++) b2[j] = *(const u64*)&Bs[cur][(c0 + j) * 18 + 2 * kp];
#pragma unroll
            for (int i = 0; i < 4; i++)
#pragma unroll
                for (int j = 0; j < 10; j++) ffma2(acc[i][j], a2[i], b2[j]);
        }
        if (hn) {
            int nxt = cur ^ 1;
            if (tid < 256) *(float4*)&As[nxt][arow * 20 + ak4 * 4] = pa;
            nb = 0;
            for (int idx = tid; idx < 800; idx += 320) {
                int col = idx >> 2, e4 = idx & 3;
                float4 v = pb[nb++];
                Bs[nxt][col * 18 + e4 * 4 + 0] = v.x; Bs[nxt][col * 18 + e4 * 4 + 1] = v.y;
                Bs[nxt][col * 18 + e4 * 4 + 2] = v.z; Bs[nxt][col * 18 + e4 * 4 + 3] = v.w;
            }
        }
        __syncthreads();
    }
#pragma unroll
    for (int i = 0; i < 4; i++)
#pragma unroll
        for (int j = 0; j < 10; j++)
            g_obs[(row0 + r0 + i) * BEL + c0 + j] = hsum2(acc[i][j]) + b_bq[c0 + j];
}

// ---------------------------------------------------------------------------
// Persistent scan (R14 frozen — current best).
// ---------------------------------------------------------------------------
#define SCAN_SMEM (18520 * 4)

__global__ __launch_bounds__(640, 1) void k_scan(
    const float* __restrict__ nonterm, const float* __restrict__ prev_state,
    const float* __restrict__ prev_belief, const float* __restrict__ actions,
    const float* __restrict__ noise_p, const float* __restrict__ noise_q,
    const float* __restrict__ b_sa, const float* __restrict__ b_ih,
    const float* __restrict__ b_hh, const float* __restrict__ b_bp,
    const float* __restrict__ b_sp, const float* __restrict__ b_sq,
    float* __restrict__ out) {
    extern __shared__ float sm[];
    float* s_sh = sm;            // 8x40 = 320
    float* hid  = sm + 320;      // 1600
    float* bel  = hid + 1600;    // 1600
    float* gig  = bel + 1600;    // 9600
    float* obs  = gig + 9600;    // 1600
    float* hp   = obs + 1600;    // 1600
    float* hq   = hp + 1600;     // 1600
    float* bias = hq + 1600;     // 120
    float* nbuf = bias + 120;    // 480

    const int tid = threadIdx.x;
    const int b0 = blockIdx.x * 8;

    float r_bsa = 0.f, r_bir = 0.f, r_biz = 0.f, r_bin = 0.f;
    float r_bhr = 0.f, r_bhz = 0.f, r_bhn = 0.f, r_bbp = 0.f;
    if (tid < 200) {
        r_bsa = b_sa[tid];
        r_bir = b_ih[tid]; r_biz = b_ih[200 + tid]; r_bin = b_ih[400 + tid];
        r_bhr = b_hh[tid]; r_bhz = b_hh[200 + tid]; r_bhn = b_hh[400 + tid];
        r_bbp = b_bp[tid];
    }
    if (tid < 120) bias[tid] = (tid < 60) ? b_sp[tid] : b_sq[tid - 60];

    for (int idx = tid; idx < 8 * BEL; idx += 640) {
        int bb = idx / BEL, j = idx - bb * BEL;
        bel[idx] = prev_belief[(size_t)(b0 + bb) * BEL + j];
    }
    if (tid < 320) {
        int bb = tid / 40, c = tid % 40;
        float v = 0.f;
        if (c < 30)      v = prev_state[(size_t)(b0 + bb) * ST + c] * nonterm[b0 + bb];
        else if (c < 38) v = actions[(size_t)(b0 + bb) * ACT + (c - 30)];
        s_sh[tid] = v;
    } else if (tid >= 320) {
        for (int i = tid - 320; i < 400; i += 320)
            *(float4*)&obs[i * 4] = *(const float4*)&g_obs[(size_t)b0 * BEL + i * 4];
    }
    __syncthreads();

    for (int t = 0; t < TT; t++) {
        // ===== PhA =====
        if (tid < 200) {
            u64 acc[8];
#pragma unroll
            for (int bb = 0; bb < 8; bb++) acc[bb] = 0ULL;
            const char* wp = (const char*)g_Wsa + tid * 16;
#pragma unroll
            for (int k4 = 0; k4 < 10; k4++) {
                ulonglong2 w = __ldg((const ulonglong2*)(wp + k4 * 3200));
                const char* sp = (const char*)s_sh + k4 * 16;
#pragma unroll
                for (int bb = 0; bb < 8; bb++) {
                    ulonglong2 s = *(const ulonglong2*)(sp + bb * 160);
                    ffma2(acc[bb], s.x, w.x);
                    ffma2(acc[bb], s.y, w.y);
                }
            }
#pragma unroll
            for (int bb = 0; bb < 8; bb++)
                hid[bb * 200 + tid] = fmaxf(hsum2(acc[bb]) + r_bsa, 0.f);
        }
        __syncthreads();

        // ===== PhB =====
        if (tid < 600) {
            const char* src = (const char*)((tid < 300) ? hid : bel);
            const char* wp = (const char*)g_Wg2 + tid * 32;
            u64 accA[8], accB[8];
#pragma unroll
            for (int bb = 0; bb < 8; bb++) { accA[bb] = 0ULL; accB[bb] = 0ULL; }
            ulonglong2 w0a = *(const ulonglong2*)wp;
            ulonglong2 w0b = *(const ulonglong2*)(wp + 16);
            ulonglong2 w1a = *(const ulonglong2*)(wp + 19200);
            ulonglong2 w1b = *(const ulonglong2*)(wp + 19216);
#pragma unroll 5
            for (int k4 = 0; k4 < 50; k4++) {
                ulonglong2 wa = w0a, wb = w0b;
                w0a = w1a; w0b = w1b;
                if (k4 + 2 < 50) {
                    w1a = *(const ulonglong2*)(wp + (k4 + 2) * 19200);
                    w1b = *(const ulonglong2*)(wp + (k4 + 2) * 19200 + 16);
                }
                const char* sp = src + k4 * 16;
#pragma unroll
                for (int bb = 0; bb < 8; bb++) {
                    ulonglong2 h = *(const ulonglong2*)(sp + bb * 800);
                    ffma2(accA[bb], h.x, wa.x); ffma2(accA[bb], h.y, wa.y);
                    ffma2(accB[bb], h.x, wb.x); ffma2(accB[bb], h.y, wb.y);
                }
            }
            int p = (tid < 300) ? tid : tid - 300;
            float* dst = (tid < 300) ? gig : (gig + 4800);
#pragma unroll
            for (int bb = 0; bb < 8; bb++) {
                dst[bb * 600 + 2 * p]     = hsum2(accA[bb]);
                dst[bb * 600 + 2 * p + 1] = hsum2(accB[bb]);
            }
        }
        __syncthreads();

        // ===== PhC =====
        if (tid < 200) {
            const int j = tid;
            const float* gh = gig + 4800;
#pragma unroll
            for (int bb = 0; bb < 8; bb++) {
                float r = sigm(gig[bb * 600 + j] + r_bir + gh[bb * 600 + j] + r_bhr);
                float z = sigm(gig[bb * 600 + 200 + j] + r_biz + gh[bb * 600 + 200 + j] + r_bhz);
                float n = tanhfast(gig[bb * 600 + 400 + j] + r_bin +
                                   r * (gh[bb * 600 + 400 + j] + r_bhn));
                float nb = (1.f - z) * n + z * bel[bb * 200 + j];
                bel[bb * 200 + j] = nb;
                out[OFF_B + ((size_t)t * BB + b0 + bb) * BEL + j] = nb;
            }
        }
        __syncthreads();

        // ===== PhD =====
        if (tid < 400) {
            const int p = tid % 200;
            const int half = tid / 200;
            const char* wp = (const char*)g_Wh2 + p * 32;
            u64 accA[8], accB[8];
#pragma unroll
            for (int bb = 0; bb < 8; bb++) { accA[bb] = 0ULL; accB[bb] = 0ULL; }
            const int kb = half * 25;
            const char* wpk = wp + kb * 6400;
            ulonglong2 w0a = *(const ulonglong2*)wpk;
            ulonglong2 w0b = *(const ulonglong2*)(wpk + 16);
            ulonglong2 w1a = *(const ulonglong2*)(wpk + 6400);
            ulonglong2 w1b = *(const ulonglong2*)(wpk + 6416);
            const char* sb = (const char*)bel + kb * 16;
#pragma unroll 5
            for (int kk = 0; kk < 25; kk++) {
                ulonglong2 wa = w0a, wb = w0b;
                w0a = w1a; w0b = w1b;
                if (kk + 2 < 25) {
                    w1a = *(const ulonglong2*)(wpk + (kk + 2) * 6400);
                    w1b = *(const ulonglong2*)(wpk + (kk + 2) * 6400 + 16);
                }
                const char* sp = sb + kk * 16;
#pragma unroll
                for (int bb = 0; bb < 8; bb++) {
                    ulonglong2 h = *(const ulonglong2*)(sp + bb * 800);
                    ffma2(accA[bb], h.x, wa.x); ffma2(accA[bb], h.y, wa.y);
                    ffma2(accB[bb], h.x, wb.x); ffma2(accB[bb], h.y, wb.y);
                }
            }
#pragma unroll
            for (int bb = 0; bb < 8; bb++) {
                gig[half * 3200 + bb * 400 + 2 * p]     = hsum2(accA[bb]);
                gig[half * 3200 + bb * 400 + 2 * p + 1] = hsum2(accB[bb]);
            }
        } else if (tid < 520) {
            int i = tid - 400;
            size_t base = ((size_t)t * BB + b0) * ST;
            if (i < 60) *(float4*)&nbuf[i * 4] = *(const float4*)&noise_p[base + i * 4];
            else {
                int j = i - 60;
                *(float4*)&nbuf[240 + j * 4] = *(const float4*)&noise_q[base + j * 4];
            }
        }
        __syncthreads();

        // ===== reduce -> hp/hq =====
        if (tid < 400) {
#pragma unroll
            for (int bb = 0; bb < 8; bb++) {
                float v = gig[bb * 400 + tid] + gig[3200 + bb * 400 + tid];
                if (tid < 200) hp[bb * 200 + tid] = fmaxf(v + r_bbp, 0.f);
                else hq[bb * 200 + tid - 200] = fmaxf(v + obs[bb * 200 + tid - 200], 0.f);
            }
        }
        __syncthreads();

        // ===== PhE =====
        if (tid < 600) {
            const int g = tid % 120, q = tid / 120;
            const float* srcf = (g < 60) ? hp : hq;
            u64 acc[8];
#pragma unroll
            for (int bb = 0; bb < 8; bb++) acc[bb] = 0ULL;
            const char* wp = (const char*)g_Wo4 + q * 19200 + g * 16;
            const char* sb = (const char*)srcf + q * 160;
#pragma unroll
            for (int kk = 0; kk < 10; kk++) {
                ulonglong2 w = __ldg((const ulonglong2*)(wp + kk * 1920));
                const char* sp = sb + kk * 16;
#pragma unroll
                for (int bb = 0; bb < 8; bb++) {
                    ulonglong2 h = *(const ulonglong2*)(sp + bb * 800);
                    ffma2(acc[bb], h.x, w.x);
                    ffma2(acc[bb], h.y, w.y);
                }
            }
#pragma unroll
            for (int bb = 0; bb < 8; bb++)
                gig[q * 960 + bb * 120 + g] = hsum2(acc[bb]);
        }
        __syncthreads();

        // ===== PhF =====
        if (tid < 240) {
            const int bb = tid / 30, i = tid - bb * 30;
            size_t gidx = ((size_t)t * BB + b0 + bb) * ST + i;
            float np = nbuf[bb * 30 + i], nq = nbuf[240 + bb * 30 + i];
            float mp = bias[i], spr = bias[30 + i], mq = bias[60 + i], sqr = bias[90 + i];
#pragma unroll
            for (int q = 0; q < 5; q++) {
                mp  += gig[q * 960 + bb * 120 + i];
                spr += gig[q * 960 + bb * 120 + 30 + i];
                mq  += gig[q * 960 + bb * 120 + 60 + i];
                sqr += gig[q * 960 + bb * 120 + 90 + i];
            }
            float spv = softplusf(spr) + 0.1f;
            float sqv = softplusf(sqr) + 0.1f;
            float po  = fmaf(sqv, nq, mq);
            out[OFF_MP + gidx] = mp;
            out[OFF_SP + gidx] = spv;
            out[OFF_PS + gidx] = fmaf(spv, np, mp);
            out[OFF_MQ + gidx] = mq;
            out[OFF_SQ + gidx] = sqv;
            out[OFF_PO + gidx] = po;
            if (t + 1 < TT)
                s_sh[bb * 40 + i] = po * nonterm[(size_t)(t + 1) * BB + b0 + bb];
        } else if (tid < 304) {
            int idx = tid - 240, bb = idx >> 3, i = idx & 7;
            if (t + 1 < TT)
                s_sh[bb * 40 + 30 + i] = actions[((size_t)(t + 1) * BB + b0 + bb) * ACT + i];
        } else if (tid >= 320) {
            if (t + 1 < TT) {
                for (int i = tid - 320; i < 400; i += 320)
                    *(float4*)&obs[i * 4] =
                        *(const float4*)&g_obs[((size_t)(t + 1) * BB + b0) * BEL + i * 4];
            }
        }
        __syncthreads();
    }
}

// ---------------------------------------------------------------------------
extern "C" void kernel_launch(void* const* d_in, const int* in_sizes, int n_in,
                              void* d_out, int out_size) {
    const float* prev_state   = (const float*)d_in[0];
    const float* actions      = (const float*)d_in[1];
    const float* prev_belief  = (const float*)d_in[2];
    const float* observations = (const float*)d_in[3];
    const float* nonterm      = (const float*)d_in[4];
    const float* noise_p      = (const float*)d_in[5];
    const float* noise_q      = (const float*)d_in[6];
    const float* W_sa = (const float*)d_in[7];  const float* b_sa = (const float*)d_in[8];
    const float* W_ih = (const float*)d_in[9];  const float* b_ih = (const float*)d_in[10];
    const float* W_hh = (const float*)d_in[11]; const float* b_hh = (const float*)d_in[12];
    const float* W_bp = (const float*)d_in[13]; const float* b_bp = (const float*)d_in[14];
    const float* W_sp = (const float*)d_in[15]; const float* b_sp = (const float*)d_in[16];
    const float* W_bq = (const float*)d_in[17]; const float* b_bq = (const float*)d_in[18];
    const float* W_sq = (const float*)d_in[19]; const float* b_sq = (const float*)d_in[20];
    float* out = (float*)d_out;
    (void)in_sizes; (void)n_in; (void)out_size;

    static int done = 0;
    if (!done) {
        cudaFuncSetAttribute(k_scan, cudaFuncAttributeMaxDynamicSharedMemorySize, SCAN_SMEM);
        done = 1;
    }
    k_prep<<<(PREP_N + 255) / 256, 256>>>(W_sa, W_ih, W_hh, W_bp, W_sp, W_bq, W_sq);
    k_mark<<<1, 32>>>();
    k_obs_gemm<<<(TT * BB) / 64, 320>>>(observations, W_bq, b_bq);
    k_scan<<<BB / 8, 640, SCAN_SMEM>>>(nonterm, prev_state, prev_belief, actions,
                                       noise_p, noise_q, b_sa, b_ih, b_hh,
                                       b_bp, b_sp, b_sq, out);
}

// round 17
// speedup vs baseline: 1.7429x; 1.0639x over previous
#include <cuda_runtime.h>
#include <math.h>

#define TT  50
#define BB  1024
#define BEL 200
#define ST  30
#define ACT 8
#define EMB 1024

static const size_t OFF_B  = 0;
static const size_t OFF_PS = (size_t)TT * BB * BEL;
static const size_t SZ30   = (size_t)TT * BB * ST;
static const size_t OFF_MP = OFF_PS + SZ30;
static const size_t OFF_SP = OFF_MP + SZ30;
static const size_t OFF_PO = OFF_SP + SZ30;
static const size_t OFF_MQ = OFF_PO + SZ30;
static const size_t OFF_SQ = OFF_MQ + SZ30;

__device__ __align__(16) float g_obs[(size_t)TT * BB * BEL];
// split-half layouts for coalesced weight LDG.128:
__device__ __align__(16) float g_Wg2[240000];  // [k4][half(2)][tc(600)][4k]; col = 2*tc+half; tc<300: W_ih else W_hh
__device__ __align__(16) float g_Wsa[8000];    // [k4(10)][j(200)][4k], K padded 38->40
__device__ __align__(16) float g_Wh2[80000];   // [k4][half(2)][p(200)][4k]; col = 2*p+half; p<100: W_bp else W_bq_b
__device__ __align__(16) float g_Wo4[24000];   // [k4][g(120)][4k]; g<60: W_sp else W_sq

typedef unsigned long long u64;

__device__ __forceinline__ void ffma2(u64& acc, u64 a, u64 b) {
    asm("fma.rn.f32x2 %0, %1, %2, %0;" : "+l"(acc) : "l"(a), "l"(b));
}
__device__ __forceinline__ float hsum2(u64 v) {
    float lo, hi;
    asm("mov.b64 {%0,%1}, %2;" : "=f"(lo), "=f"(hi) : "l"(v));
    return lo + hi;
}
__device__ __forceinline__ float sigm(float x) { return 1.f / (1.f + __expf(-x)); }
__device__ __forceinline__ float tanhfast(float x) { return 1.f - 2.f / (__expf(2.f * x) + 1.f); }
__device__ __forceinline__ float softplusf(float x) {
    return fmaxf(x, 0.f) + log1pf(__expf(-fabsf(x)));
}

// ---------------------------------------------------------------------------
#define PREP_N 352000
__global__ void k_prep(const float* __restrict__ W_sa, const float* __restrict__ W_ih,
                       const float* __restrict__ W_hh, const float* __restrict__ W_bp,
                       const float* __restrict__ W_sp, const float* __restrict__ W_bq,
                       const float* __restrict__ W_sq) {
    int idx = blockIdx.x * blockDim.x + threadIdx.x;
    if (idx >= PREP_N) return;
    if (idx < 240000) {  // g_Wg2 split-half: [k4][half][tc][4k]
        int l = idx;
        int k4 = l / 4800, r = l % 4800;
        int half = r / 2400, r2 = r % 2400;
        int tc = r2 >> 2, kk = r2 & 3, k = 4 * k4 + kk;
        g_Wg2[idx] = (tc < 300) ? W_ih[(2 * tc + half) * 200 + k]
                                : W_hh[(2 * (tc - 300) + half) * 200 + k];
        return;
    }
    idx -= 240000;
    if (idx < 8000) {    // g_Wsa
        int kk = idx & 3, t = idx >> 2;
        int j = t % 200, k4 = t / 200, k = 4 * k4 + kk;
        g_Wsa[idx] = (k < 38) ? W_sa[j * 38 + k] : 0.f;
        return;
    }
    idx -= 8000;
    if (idx < 80000) {   // g_Wh2 split-half: [k4][half][p][4k]
        int l = idx;
        int k4 = l / 1600, r = l % 1600;
        int half = r / 800, r2 = r % 800;
        int p = r2 >> 2, kk = r2 & 3, k = 4 * k4 + kk;
        g_Wh2[idx] = (p < 100) ? W_bp[(2 * p + half) * 200 + k]
                               : W_bq[(size_t)(2 * (p - 100) + half) * 1224 + k];
        return;
    }
    idx -= 80000;
    {                    // g_Wo4
        int kk = idx & 3, t = idx >> 2;
        int g = t % 120, k4 = t / 120, k = 4 * k4 + kk;
        g_Wo4[idx] = (g < 60) ? W_sp[g * 200 + k] : W_sq[(g - 60) * 200 + k];
    }
}

// ncu-window alignment dummy (4-kernel graphs profile the 4th kernel = k_scan).
__global__ void k_mark() {}

// ---------------------------------------------------------------------------
// Obs GEMM (R3/R14/R16-proven, 320 threads, tile 4x10, double-buffered).
// ---------------------------------------------------------------------------
__global__ __launch_bounds__(320, 1) void k_obs_gemm(const float* __restrict__ A,
                                                     const float* __restrict__ W_bq,
                                                     const float* __restrict__ b_bq) {
    __shared__ __align__(16) float As[2][64 * 20];
    __shared__ __align__(16) float Bs[2][200 * 18];
    const int tid = threadIdx.x;
    const size_t row0 = (size_t)blockIdx.x * 64;
    const int r0 = (tid / 20) * 4, c0 = (tid % 20) * 10;
    u64 acc[4][10];
#pragma unroll
    for (int i = 0; i < 4; i++)
#pragma unroll
        for (int j = 0; j < 10; j++) acc[i][j] = 0ULL;
    const int arow = tid >> 2, ak4 = tid & 3;
    if (tid < 256)
        *(float4*)&As[0][arow * 20 + ak4 * 4] = *(const float4*)&A[(row0 + arow) * EMB + ak4 * 4];
    for (int idx = tid; idx < 800; idx += 320) {
        int col = idx >> 2, e4 = idx & 3;
        float4 v = *(const float4*)&W_bq[(size_t)col * 1224 + 200 + e4 * 4];
        Bs[0][col * 18 + e4 * 4 + 0] = v.x; Bs[0][col * 18 + e4 * 4 + 1] = v.y;
        Bs[0][col * 18 + e4 * 4 + 2] = v.z; Bs[0][col * 18 + e4 * 4 + 3] = v.w;
    }
    __syncthreads();
    for (int kti = 0; kti < 64; kti++) {
        const int cur = kti & 1;
        const bool hn = (kti + 1) < 64;
        float4 pa; float4 pb[3]; int nb = 0;
        if (hn) {
            int kt = (kti + 1) * 16;
            if (tid < 256) pa = *(const float4*)&A[(row0 + arow) * EMB + kt + ak4 * 4];
            for (int idx = tid; idx < 800; idx += 320) {
                int col = idx >> 2, e4 = idx & 3;
                pb[nb++] = *(const float4*)&W_bq[(size_t)col * 1224 + 200 + kt + e4 * 4];
            }
        }
#pragma unroll
        for (int kp = 0; kp < 8; kp++) {
            u64 a2[4], b2[10];
#pragma unroll
            for (int i = 0; i < 4; i++) a2[i] = *(const u64*)&As[cur][(r0 + i) * 20 + 2 * kp];
#pragma unroll
            for (int j = 0; j < 10; j++) b2[j] = *(const u64*)&Bs[cur][(c0 + j) * 18 + 2 * kp];
#pragma unroll
            for (int i = 0; i < 4; i++)
#pragma unroll
                for (int j = 0; j < 10; j++) ffma2(acc[i][j], a2[i], b2[j]);
        }
        if (hn) {
            int nxt = cur ^ 1;
            if (tid < 256) *(float4*)&As[nxt][arow * 20 + ak4 * 4] = pa;
            nb = 0;
            for (int idx = tid; idx < 800; idx += 320) {
                int col = idx >> 2, e4 = idx & 3;
                float4 v = pb[nb++];
                Bs[nxt][col * 18 + e4 * 4 + 0] = v.x; Bs[nxt][col * 18 + e4 * 4 + 1] = v.y;
                Bs[nxt][col * 18 + e4 * 4 + 2] = v.z; Bs[nxt][col * 18 + e4 * 4 + 3] = v.w;
            }
        }
        __syncthreads();
    }
#pragma unroll
    for (int i = 0; i < 4; i++)
#pragma unroll
        for (int j = 0; j < 10; j++)
            g_obs[(row0 + r0 + i) * BEL + c0 + j] = hsum2(acc[i][j]) + b_bq[c0 + j];
}

// ---------------------------------------------------------------------------
// Persistent scan (R16 structure; only weight byte-offsets changed for the
// split-half coalesced layouts).
// ---------------------------------------------------------------------------
#define SCAN_SMEM (18520 * 4)

__global__ __launch_bounds__(640, 1) void k_scan(
    const float* __restrict__ nonterm, const float* __restrict__ prev_state,
    const float* __restrict__ prev_belief, const float* __restrict__ actions,
    const float* __restrict__ noise_p, const float* __restrict__ noise_q,
    const float* __restrict__ b_sa, const float* __restrict__ b_ih,
    const float* __restrict__ b_hh, const float* __restrict__ b_bp,
    const float* __restrict__ b_sp, const float* __restrict__ b_sq,
    float* __restrict__ out) {
    extern __shared__ float sm[];
    float* s_sh = sm;            // 8x40 = 320
    float* hid  = sm + 320;      // 1600
    float* bel  = hid + 1600;    // 1600
    float* gig  = bel + 1600;    // 9600
    float* obs  = gig + 9600;    // 1600
    float* hp   = obs + 1600;    // 1600
    float* hq   = hp + 1600;     // 1600
    float* bias = hq + 1600;     // 120
    float* nbuf = bias + 120;    // 480

    const int tid = threadIdx.x;
    const int b0 = blockIdx.x * 8;

    float r_bsa = 0.f, r_bir = 0.f, r_biz = 0.f, r_bin = 0.f;
    float r_bhr = 0.f, r_bhz = 0.f, r_bhn = 0.f, r_bbp = 0.f;
    if (tid < 200) {
        r_bsa = b_sa[tid];
        r_bir = b_ih[tid]; r_biz = b_ih[200 + tid]; r_bin = b_ih[400 + tid];
        r_bhr = b_hh[tid]; r_bhz = b_hh[200 + tid]; r_bhn = b_hh[400 + tid];
        r_bbp = b_bp[tid];
    }
    if (tid < 120) bias[tid] = (tid < 60) ? b_sp[tid] : b_sq[tid - 60];

    for (int idx = tid; idx < 8 * BEL; idx += 640) {
        int bb = idx / BEL, j = idx - bb * BEL;
        bel[idx] = prev_belief[(size_t)(b0 + bb) * BEL + j];
    }
    if (tid < 320) {
        int bb = tid / 40, c = tid % 40;
        float v = 0.f;
        if (c < 30)      v = prev_state[(size_t)(b0 + bb) * ST + c] * nonterm[b0 + bb];
        else if (c < 38) v = actions[(size_t)(b0 + bb) * ACT + (c - 30)];
        s_sh[tid] = v;
    } else if (tid >= 320) {
        for (int i = tid - 320; i < 400; i += 320)
            *(float4*)&obs[i * 4] = *(const float4*)&g_obs[(size_t)b0 * BEL + i * 4];
    }
    __syncthreads();

    for (int t = 0; t < TT; t++) {
        // ===== PhA =====
        if (tid < 200) {
            u64 acc[8];
#pragma unroll
            for (int bb = 0; bb < 8; bb++) acc[bb] = 0ULL;
            const char* wp = (const char*)g_Wsa + tid * 16;
#pragma unroll
            for (int k4 = 0; k4 < 10; k4++) {
                ulonglong2 w = __ldg((const ulonglong2*)(wp + k4 * 3200));
                const char* sp = (const char*)s_sh + k4 * 16;
#pragma unroll
                for (int bb = 0; bb < 8; bb++) {
                    ulonglong2 s = *(const ulonglong2*)(sp + bb * 160);
                    ffma2(acc[bb], s.x, w.x);
                    ffma2(acc[bb], s.y, w.y);
                }
            }
#pragma unroll
            for (int bb = 0; bb < 8; bb++)
                hid[bb * 200 + tid] = fmaxf(hsum2(acc[bb]) + r_bsa, 0.f);
        }
        __syncthreads();

        // ===== PhB: split-half weight planes (wa at +0, wb at +9600B) =====
        if (tid < 600) {
            const char* src = (const char*)((tid < 300) ? hid : bel);
            const char* wp = (const char*)g_Wg2 + tid * 16;   // per-k4 stride 19200B
            u64 accA[8], accB[8];
#pragma unroll
            for (int bb = 0; bb < 8; bb++) { accA[bb] = 0ULL; accB[bb] = 0ULL; }
            ulonglong2 w0a = *(const ulonglong2*)wp;
            ulonglong2 w0b = *(const ulonglong2*)(wp + 9600);
            ulonglong2 w1a = *(const ulonglong2*)(wp + 19200);
            ulonglong2 w1b = *(const ulonglong2*)(wp + 19200 + 9600);
#pragma unroll 5
            for (int k4 = 0; k4 < 50; k4++) {
                ulonglong2 wa = w0a, wb = w0b;
                w0a = w1a; w0b = w1b;
                if (k4 + 2 < 50) {
                    w1a = *(const ulonglong2*)(wp + (k4 + 2) * 19200);
                    w1b = *(const ulonglong2*)(wp + (k4 + 2) * 19200 + 9600);
                }
                const char* sp = src + k4 * 16;
#pragma unroll
                for (int bb = 0; bb < 8; bb++) {
                    ulonglong2 h = *(const ulonglong2*)(sp + bb * 800);
                    ffma2(accA[bb], h.x, wa.x); ffma2(accA[bb], h.y, wa.y);
                    ffma2(accB[bb], h.x, wb.x); ffma2(accB[bb], h.y, wb.y);
                }
            }
            int p = (tid < 300) ? tid : tid - 300;
            float* dst = (tid < 300) ? gig : (gig + 4800);
#pragma unroll
            for (int bb = 0; bb < 8; bb++) {
                dst[bb * 600 + 2 * p]     = hsum2(accA[bb]);
                dst[bb * 600 + 2 * p + 1] = hsum2(accB[bb]);
            }
        }
        __syncthreads();

        // ===== PhC =====
        if (tid < 200) {
            const int j = tid;
            const float* gh = gig + 4800;
#pragma unroll
            for (int bb = 0; bb < 8; bb++) {
                float r = sigm(gig[bb * 600 + j] + r_bir + gh[bb * 600 + j] + r_bhr);
                float z = sigm(gig[bb * 600 + 200 + j] + r_biz + gh[bb * 600 + 200 + j] + r_bhz);
                float n = tanhfast(gig[bb * 600 + 400 + j] + r_bin +
                                   r * (gh[bb * 600 + 400 + j] + r_bhn));
                float nb = (1.f - z) * n + z * bel[bb * 200 + j];
                bel[bb * 200 + j] = nb;
                out[OFF_B + ((size_t)t * BB + b0 + bb) * BEL + j] = nb;
            }
        }
        __syncthreads();

        // ===== PhD: split-half weight planes (wa at +0, wb at +3200B) =====
        if (tid < 400) {
            const int p = tid % 200;
            const int half = tid / 200;
            const char* wp = (const char*)g_Wh2 + p * 16;   // per-k4 stride 6400B
            u64 accA[8], accB[8];
#pragma unroll
            for (int bb = 0; bb < 8; bb++) { accA[bb] = 0ULL; accB[bb] = 0ULL; }
            const int kb = half * 25;
            const char* wpk = wp + kb * 6400;
            ulonglong2 w0a = *(const ulonglong2*)wpk;
            ulonglong2 w0b = *(const ulonglong2*)(wpk + 3200);
            ulonglong2 w1a = *(const ulonglong2*)(wpk + 6400);
            ulonglong2 w1b = *(const ulonglong2*)(wpk + 6400 + 3200);
            const char* sb = (const char*)bel + kb * 16;
#pragma unroll 5
            for (int kk = 0; kk < 25; kk++) {
                ulonglong2 wa = w0a, wb = w0b;
                w0a = w1a; w0b = w1b;
                if (kk + 2 < 25) {
                    w1a = *(const ulonglong2*)(wpk + (kk + 2) * 6400);
                    w1b = *(const ulonglong2*)(wpk + (kk + 2) * 6400 + 3200);
                }
                const char* sp = sb + kk * 16;
#pragma unroll
                for (int bb = 0; bb < 8; bb++) {
                    ulonglong2 h = *(const ulonglong2*)(sp + bb * 800);
                    ffma2(accA[bb], h.x, wa.x); ffma2(accA[bb], h.y, wa.y);
                    ffma2(accB[bb], h.x, wb.x); ffma2(accB[bb], h.y, wb.y);
                }
            }
#pragma unroll
            for (int bb = 0; bb < 8; bb++) {
                gig[half * 3200 + bb * 400 + 2 * p]     = hsum2(accA[bb]);
                gig[half * 3200 + bb * 400 + 2 * p + 1] = hsum2(accB[bb]);
            }
        } else if (tid < 520) {
            int i = tid - 400;
            size_t base = ((size_t)t * BB + b0) * ST;
            if (i < 60) *(float4*)&nbuf[i * 4] = *(const float4*)&noise_p[base + i * 4];
            else {
                int j = i - 60;
                *(float4*)&nbuf[240 + j * 4] = *(const float4*)&noise_q[base + j * 4];
            }
        }
        __syncthreads();

        // ===== reduce -> hp/hq =====
        if (tid < 400) {
#pragma unroll
            for (int bb = 0; bb < 8; bb++) {
                float v = gig[bb * 400 + tid] + gig[3200 + bb * 400 + tid];
                if (tid < 200) hp[bb * 200 + tid] = fmaxf(v + r_bbp, 0.f);
                else hq[bb * 200 + tid - 200] = fmaxf(v + obs[bb * 200 + tid - 200], 0.f);
            }
        }
        __syncthreads();

        // ===== PhE =====
        if (tid < 600) {
            const int g = tid % 120, q = tid / 120;
            const float* srcf = (g < 60) ? hp : hq;
            u64 acc[8];
#pragma unroll
            for (int bb = 0; bb < 8; bb++) acc[bb] = 0ULL;
            const char* wp = (const char*)g_Wo4 + q * 19200 + g * 16;
            const char* sb = (const char*)srcf + q * 160;
#pragma unroll
            for (int kk = 0; kk < 10; kk++) {
                ulonglong2 w = __ldg((const ulonglong2*)(wp + kk * 1920));
                const char* sp = sb + kk * 16;
#pragma unroll
                for (int bb = 0; bb < 8; bb++) {
                    ulonglong2 h = *(const ulonglong2*)(sp + bb * 800);
                    ffma2(acc[bb], h.x, w.x);
                    ffma2(acc[bb], h.y, w.y);
                }
            }
#pragma unroll
            for (int bb = 0; bb < 8; bb++)
                gig[q * 960 + bb * 120 + g] = hsum2(acc[bb]);
        }
        __syncthreads();

        // ===== PhF =====
        if (tid < 240) {
            const int bb = tid / 30, i = tid - bb * 30;
            size_t gidx = ((size_t)t * BB + b0 + bb) * ST + i;
            float np = nbuf[bb * 30 + i], nq = nbuf[240 + bb * 30 + i];
            float mp = bias[i], spr = bias[30 + i], mq = bias[60 + i], sqr = bias[90 + i];
#pragma unroll
            for (int q = 0; q < 5; q++) {
                mp  += gig[q * 960 + bb * 120 + i];
                spr += gig[q * 960 + bb * 120 + 30 + i];
                mq  += gig[q * 960 + bb * 120 + 60 + i];
                sqr += gig[q * 960 + bb * 120 + 90 + i];
            }
            float spv = softplusf(spr) + 0.1f;
            float sqv = softplusf(sqr) + 0.1f;
            float po  = fmaf(sqv, nq, mq);
            out[OFF_MP + gidx] = mp;
            out[OFF_SP + gidx] = spv;
            out[OFF_PS + gidx] = fmaf(spv, np, mp);
            out[OFF_MQ + gidx] = mq;
            out[OFF_SQ + gidx] = sqv;
            out[OFF_PO + gidx] = po;
            if (t + 1 < TT)
                s_sh[bb * 40 + i] = po * nonterm[(size_t)(t + 1) * BB + b0 + bb];
        } else if (tid < 304) {
            int idx = tid - 240, bb = idx >> 3, i = idx & 7;
            if (t + 1 < TT)
                s_sh[bb * 40 + 30 + i] = actions[((size_t)(t + 1) * BB + b0 + bb) * ACT + i];
        } else if (tid >= 320) {
            if (t + 1 < TT) {
                for (int i = tid - 320; i < 400; i += 320)
                    *(float4*)&obs[i * 4] =
                        *(const float4*)&g_obs[((size_t)(t + 1) * BB + b0) * BEL + i * 4];
            }
        }
        __syncthreads();
    }
}

// ---------------------------------------------------------------------------
extern "C" void kernel_launch(void* const* d_in, const int* in_sizes, int n_in,
                              void* d_out, int out_size) {
    const float* prev_state   = (const float*)d_in[0];
    const float* actions      = (const float*)d_in[1];
    const float* prev_belief  = (const float*)d_in[2];
    const float* observations = (const float*)d_in[3];
    const float* nonterm      = (const float*)d_in[4];
    const float* noise_p      = (const float*)d_in[5];
    const float* noise_q      = (const float*)d_in[6];
    const float* W_sa = (const float*)d_in[7];  const float* b_sa = (const float*)d_in[8];
    const float* W_ih = (const float*)d_in[9];  const float* b_ih = (const float*)d_in[10];
    const float* W_hh = (const float*)d_in[11]; const float* b_hh = (const float*)d_in[12];
    const float* W_bp = (const float*)d_in[13]; const float* b_bp = (const float*)d_in[14];
    const float* W_sp = (const float*)d_in[15]; const float* b_sp = (const float*)d_in[16];
    const float* W_bq = (const float*)d_in[17]; const float* b_bq = (const float*)d_in[18];
    const float* W_sq = (const float*)d_in[19]; const float* b_sq = (const float*)d_in[20];
    float* out = (float*)d_out;
    (void)in_sizes; (void)n_in; (void)out_size;

    static int done = 0;
    if (!done) {
        cudaFuncSetAttribute(k_scan, cudaFuncAttributeMaxDynamicSharedMemorySize, SCAN_SMEM);
        done = 1;
    }
    k_prep<<<(PREP_N + 255) / 256, 256>>>(W_sa, W_ih, W_hh, W_bp, W_sp, W_bq, W_sq);
    k_mark<<<1, 32>>>();
    k_obs_gemm<<<(TT * BB) / 64, 320>>>(observations, W_bq, b_bq);
    k_scan<<<BB / 8, 640, SCAN_SMEM>>>(nonterm, prev_state, prev_belief, actions,
                                       noise_p, noise_q, b_sa, b_ih, b_hh,
                                       b_bp, b_sp, b_sq, out);
}